// round 3
// baseline (speedup 1.0000x reference)
#include <cuda_runtime.h>

#define T_ 512
#define K_ 8
#define D_ 8
#define NB 4

static constexpr int TK = T_ * K_;

// Per-(t,k) precomputed parameters (device scratch — no allocation)
__device__ float g_Q[TK * 64];     // [tk][i*8+j]  rotation (bias-folded form uses same Q)
__device__ float g_bias[TK * 8];   // [tk][j]      = -(center . Q)_j
__device__ float g_c1[TK * 8];     // [tk][d]      = -0.5 / var
__device__ float g_lc0[TK * 8];    // [tk][d]      = -0.5*ln(2*pi*var)
__device__ float g_w[TK];          // [t][k]       softmax weights

// ---------- packed f32x2 helpers ----------
typedef unsigned long long u64_t;

static __device__ __forceinline__ u64_t pk2(float lo, float hi) {
    u64_t r;
    asm("mov.b64 %0, {%1, %2};" : "=l"(r) : "f"(lo), "f"(hi));
    return r;
}
static __device__ __forceinline__ void upk2(u64_t v, float& lo, float& hi) {
    asm("mov.b64 {%0, %1}, %2;" : "=f"(lo), "=f"(hi) : "l"(v));
}
static __device__ __forceinline__ u64_t fma2_(u64_t a, u64_t b, u64_t c) {
    u64_t d;
    asm("fma.rn.f32x2 %0, %1, %2, %3;" : "=l"(d) : "l"(a), "l"(b), "l"(c));
    return d;
}
static __device__ __forceinline__ u64_t mul2_(u64_t a, u64_t b) {
    u64_t d;
    asm("mul.rn.f32x2 %0, %1, %2;" : "=l"(d) : "l"(a), "l"(b));
    return d;
}

// ============================================================================
// Precompute: per (t,k) Cayley rotation Q, bias, variance terms; per t softmax.
// ============================================================================
__global__ void precompute_kernel(const float* __restrict__ centers,
                                  const float* __restrict__ wlog,
                                  const float* __restrict__ logvar,
                                  const float* __restrict__ cov)
{
    int tk = blockIdx.x * blockDim.x + threadIdx.x;

    // Softmax of clipped weight logits (one thread per t)
    if (tk < T_) {
        float l[K_];
        float mx = -1e30f;
        #pragma unroll
        for (int k = 0; k < K_; k++) {
            float v = wlog[tk * K_ + k];
            v = fminf(fmaxf(v, -3.5f), 3.5f);
            l[k] = v;
            mx = fmaxf(mx, v);
        }
        float s = 0.f;
        #pragma unroll
        for (int k = 0; k < K_; k++) { l[k] = __expf(l[k] - mx); s += l[k]; }
        float inv = 1.0f / s;
        #pragma unroll
        for (int k = 0; k < K_; k++) g_w[tk * K_ + k] = l[k] * inv;
    }

    if (tk >= TK) return;

    // ---- build antisymmetric A from cov_param (28 values) ----
    const float* v = cov + tk * 28;
    float flat[64];
    #pragma unroll
    for (int i = 0; i < 28; i++) { flat[i] = v[i]; flat[28 + i] = v[27 - i]; }
    #pragma unroll
    for (int i = 56; i < 64; i++) flat[i] = 0.f;

    float A[8][8];
    #pragma unroll
    for (int r = 0; r < 8; r++) {
        #pragma unroll
        for (int c = 0; c < 8; c++) {
            float ut_rc = (c > r) ? flat[8 * r + c] : 0.f;   // strict upper of a
            float ut_cr = (r > c) ? flat[8 * c + r] : 0.f;   // transpose element
            A[r][c] = 0.5f * (ut_cr - ut_rc);
        }
    }

    // ---- invert (I + A) via Gauss-Jordan with partial pivoting ----
    float M[8][8], X[8][8];
    for (int r = 0; r < 8; r++)
        for (int c = 0; c < 8; c++) {
            M[r][c] = A[r][c] + ((r == c) ? 1.f : 0.f);
            X[r][c] = (r == c) ? 1.f : 0.f;
        }
    for (int col = 0; col < 8; col++) {
        int p = col;
        float best = fabsf(M[col][col]);
        for (int r = col + 1; r < 8; r++) {
            float av = fabsf(M[r][col]);
            if (av > best) { best = av; p = r; }
        }
        if (p != col) {
            for (int j = 0; j < 8; j++) {
                float tmp = M[col][j]; M[col][j] = M[p][j]; M[p][j] = tmp;
                tmp = X[col][j]; X[col][j] = X[p][j]; X[p][j] = tmp;
            }
        }
        float pivinv = 1.0f / M[col][col];
        for (int j = 0; j < 8; j++) { M[col][j] *= pivinv; X[col][j] *= pivinv; }
        for (int r = 0; r < 8; r++) {
            if (r == col) continue;
            float f = M[r][col];
            for (int j = 0; j < 8; j++) {
                M[r][j] = fmaf(-f, M[col][j], M[r][j]);
                X[r][j] = fmaf(-f, X[col][j], X[r][j]);
            }
        }
    }

    // ---- Q = (I - A) * inv(I + A) ----
    float q[8][8];
    for (int r = 0; r < 8; r++)
        for (int c = 0; c < 8; c++) {
            float s = 0.f;
            for (int m = 0; m < 8; m++) {
                float lhs = ((r == m) ? 1.f : 0.f) - A[r][m];
                s = fmaf(lhs, X[m][c], s);
            }
            q[r][c] = s;
        }

    float* Qo = g_Q + tk * 64;
    for (int r = 0; r < 8; r++)
        for (int c = 0; c < 8; c++)
            Qo[r * 8 + c] = q[r][c];

    // bias_j = -(center . Q)_j  (folds the center subtraction into the matvec)
    const float* cc = centers + tk * 8;
    for (int j = 0; j < 8; j++) {
        float s = 0.f;
        for (int i = 0; i < 8; i++) s = fmaf(cc[i], q[i][j], s);
        g_bias[tk * 8 + j] = -s;
    }

    // variance terms
    const float LOG2PI = 1.8378770664093453f;
    for (int d = 0; d < 8; d++) {
        float lv = logvar[tk * 8 + d];
        lv = fminf(fmaxf(lv, -3.5f), 3.5f);
        g_c1[tk * 8 + d]  = -0.5f * expf(-lv);          // -0.5/var
        g_lc0[tk * 8 + d] = -0.5f * (LOG2PI + lv);      // log norm_coeff
    }
}

// ============================================================================
// Main kernel: one block per (b-chunk, t); each thread computes NB=4 outputs.
// p[b,t] = sum_k w[t,k] * prod_d ( exp(c1*xt_d^2 + lc0) + 1e-7 )
// xt = x . Q + bias, computed with packed fma.rn.f32x2.
// Product carried at 2^80 scale to avoid intermediate underflow; rescaled at end.
// ============================================================================
__global__ void __launch_bounds__(128)
pecd_main_kernel(const float* __restrict__ x, float* __restrict__ out)
{
    const int t   = blockIdx.y;
    const int tid = threadIdx.x;

    __shared__ __align__(16) float sQ[K_ * 64];
    __shared__ __align__(16) float sB[K_ * 8];
    __shared__ __align__(16) float sC[K_ * 8];
    __shared__ __align__(16) float sL[K_ * 8];
    __shared__ float sW[K_];

    {
        const float* gq = g_Q + t * (K_ * 64);
        for (int i = tid; i < K_ * 64; i += 128) sQ[i] = gq[i];
        if (tid < 64) {
            sB[tid] = g_bias[t * 64 + tid];
            sC[tid] = g_c1[t * 64 + tid];
            sL[tid] = g_lc0[t * 64 + tid];
        }
        if (tid < K_) sW[tid] = g_w[t * K_ + tid];
    }
    __syncthreads();

    const int b0 = blockIdx.x * (128 * NB) + tid;

    // load x rows: each (b,t) row is 8 floats = one aligned 32B sector
    float xr[NB][8];
    const float4* x4 = reinterpret_cast<const float4*>(x);
    #pragma unroll
    for (int ib = 0; ib < NB; ib++) {
        const int b = b0 + ib * 128;
        const float4 p0 = x4[(size_t)(b * T_ + t) * 2 + 0];
        const float4 p1 = x4[(size_t)(b * T_ + t) * 2 + 1];
        xr[ib][0] = p0.x; xr[ib][1] = p0.y; xr[ib][2] = p0.z; xr[ib][3] = p0.w;
        xr[ib][4] = p1.x; xr[ib][5] = p1.y; xr[ib][6] = p1.z; xr[ib][7] = p1.w;
    }

    float acc[NB];
    #pragma unroll
    for (int ib = 0; ib < NB; ib++) acc[ib] = 0.f;

    #pragma unroll
    for (int k = 0; k < K_; k++) {
        const float4* q4 = reinterpret_cast<const float4*>(&sQ[k * 64]);

        // bias pairs
        const float4 bb0 = reinterpret_cast<const float4*>(&sB[k * 8])[0];
        const float4 bb1 = reinterpret_cast<const float4*>(&sB[k * 8])[1];
        u64_t bias01 = pk2(bb0.x, bb0.y), bias23 = pk2(bb0.z, bb0.w);
        u64_t bias45 = pk2(bb1.x, bb1.y), bias67 = pk2(bb1.z, bb1.w);

        u64_t xt[NB][4];
        #pragma unroll
        for (int ib = 0; ib < NB; ib++) {
            xt[ib][0] = bias01; xt[ib][1] = bias23;
            xt[ib][2] = bias45; xt[ib][3] = bias67;
        }

        // xt_j += sum_i x_i * Q[i][j]   (packed over j-pairs)
        #pragma unroll
        for (int i = 0; i < 8; i++) {
            const float4 qa = q4[2 * i + 0];
            const float4 qb = q4[2 * i + 1];
            const u64_t q01 = pk2(qa.x, qa.y), q23 = pk2(qa.z, qa.w);
            const u64_t q45 = pk2(qb.x, qb.y), q67 = pk2(qb.z, qb.w);
            #pragma unroll
            for (int ib = 0; ib < NB; ib++) {
                const u64_t xi = pk2(xr[ib][i], xr[ib][i]);
                xt[ib][0] = fma2_(xi, q01, xt[ib][0]);
                xt[ib][1] = fma2_(xi, q23, xt[ib][1]);
                xt[ib][2] = fma2_(xi, q45, xt[ib][2]);
                xt[ib][3] = fma2_(xi, q67, xt[ib][3]);
            }
        }

        // gaussian product
        const float4 c0 = reinterpret_cast<const float4*>(&sC[k * 8])[0];
        const float4 c1 = reinterpret_cast<const float4*>(&sC[k * 8])[1];
        const float4 l0 = reinterpret_cast<const float4*>(&sL[k * 8])[0];
        const float4 l1 = reinterpret_cast<const float4*>(&sL[k * 8])[1];
        u64_t cp[4], lp[4];
        cp[0] = pk2(c0.x, c0.y); cp[1] = pk2(c0.z, c0.w);
        cp[2] = pk2(c1.x, c1.y); cp[3] = pk2(c1.z, c1.w);
        lp[0] = pk2(l0.x, l0.y); lp[1] = pk2(l0.z, l0.w);
        lp[2] = pk2(l1.x, l1.y); lp[3] = pk2(l1.z, l1.w);

        const float wk = sW[k];

        #pragma unroll
        for (int ib = 0; ib < NB; ib++) {
            float prod = 0x1p80f;   // scale guard against intermediate underflow
            #pragma unroll
            for (int jp = 0; jp < 4; jp++) {
                const u64_t t2 = mul2_(xt[ib][jp], xt[ib][jp]);
                const u64_t ar = fma2_(cp[jp], t2, lp[jp]);
                float a0, a1;
                upk2(ar, a0, a1);
                const float g0 = __expf(a0) + 1e-7f;
                const float g1 = __expf(a1) + 1e-7f;
                prod *= g0 * g1;
            }
            acc[ib] = fmaf(wk, prod, acc[ib]);
        }
    }

    #pragma unroll
    for (int ib = 0; ib < NB; ib++) {
        const int b = b0 + ib * 128;
        out[(size_t)b * T_ + t] = acc[ib] * 0x1p-80f;
    }
}

// ============================================================================
extern "C" void kernel_launch(void* const* d_in, const int* in_sizes, int n_in,
                              void* d_out, int out_size)
{
    const float* x       = (const float*)d_in[0];  // [B, T, D]
    const float* centers = (const float*)d_in[1];  // [T, K, D]
    const float* wlog    = (const float*)d_in[2];  // [T, K]
    const float* logvar  = (const float*)d_in[3];  // [T, K, D]
    const float* cov     = (const float*)d_in[4];  // [T, K, 28]

    const int B = in_sizes[0] / (T_ * D_);         // 2048

    precompute_kernel<<<(TK + 127) / 128, 128>>>(centers, wlog, logvar, cov);

    dim3 grid(B / (128 * NB), T_);                 // (4, 512)
    pecd_main_kernel<<<grid, 128>>>(x, (float*)d_out);
}